// round 11
// baseline (speedup 1.0000x reference)
#include <cuda_runtime.h>
#include <cuda_bf16.h>
#include <cuda_fp16.h>
#include <math.h>

#define NB 4
#define NS 4096
#define NN 128
#define TD 1024
#define SD 512
#define PD 512
#define NH 4
#define HD 128
#define NTOK (NB*NS)

// ---------------- static device scratch (no runtime alloc allowed) ----------
__device__ __align__(16) __nv_bfloat16 g_Ahi[NTOK*TD];        // 32 MB
__device__ __align__(16) __nv_bfloat16 g_Alo[NTOK*TD];        // 32 MB
__device__ __align__(16) float g_sn[NB*NN*SD];                // 1 MB
__device__ __align__(16) float g_kfull[NB*NN*PD];             // 1 MB
__device__ float g_qpart[16*PD];
__device__ float g_qconst[PD];
__device__ float g_biasv[NB*PD];
__device__ __align__(16) __nv_bfloat16 g_Chi[NB*NH*TD*HD];    // 4 MB  [b][h][k][n]
__device__ __align__(16) __nv_bfloat16 g_Clo[NB*NH*TD*HD];    // 4 MB
__device__ __align__(16) __half g_w[(size_t)NB*NH*NS*NN];     // 16 MB (fp16 weights)
__device__ float g_entpart[2048];

// ---------------- PTX helpers ----------------------------------------------
__device__ __forceinline__ void ldsm4(unsigned r[4], const void* p) {
    unsigned a = (unsigned)__cvta_generic_to_shared(p);
    asm volatile("ldmatrix.sync.aligned.m8n8.x4.shared.b16 {%0,%1,%2,%3}, [%4];"
                 : "=r"(r[0]), "=r"(r[1]), "=r"(r[2]), "=r"(r[3]) : "r"(a));
}
__device__ __forceinline__ void ldsm4t(unsigned* r, const void* p) {
    unsigned a = (unsigned)__cvta_generic_to_shared(p);
    asm volatile("ldmatrix.sync.aligned.m8n8.x4.trans.shared.b16 {%0,%1,%2,%3}, [%4];"
                 : "=r"(r[0]), "=r"(r[1]), "=r"(r[2]), "=r"(r[3]) : "r"(a));
}
__device__ __forceinline__ void mma_bf16(float c[4], const unsigned a[4], const unsigned b[2]) {
    asm volatile("mma.sync.aligned.m16n8k16.row.col.f32.bf16.bf16.f32 "
                 "{%0,%1,%2,%3},{%4,%5,%6,%7},{%8,%9},{%0,%1,%2,%3};"
                 : "+f"(c[0]), "+f"(c[1]), "+f"(c[2]), "+f"(c[3])
                 : "r"(a[0]), "r"(a[1]), "r"(a[2]), "r"(a[3]), "r"(b[0]), "r"(b[1]));
}
__device__ __forceinline__ void cpa16(void* s, const void* g) {
    unsigned sa = (unsigned)__cvta_generic_to_shared(s);
    asm volatile("cp.async.cg.shared.global [%0],[%1],16;" :: "r"(sa), "l"(g) : "memory");
}
#define CP_COMMIT() asm volatile("cp.async.commit_group;" ::: "memory")
#define CP_WAIT1()  asm volatile("cp.async.wait_group 1;"  ::: "memory")

// ============================================================================
// prepA: state LN (512 blocks) | qconst split-K partials (32 blocks)
// ============================================================================
__global__ void prepA_kernel(const float* __restrict__ st,
                             const float* __restrict__ lnsg, const float* __restrict__ lnsb,
                             const float* __restrict__ Wq, const float* __restrict__ bt) {
    int bid = blockIdx.x, t = threadIdx.x;
    if (bid < NB * NN) {
        int row = bid;
        const float2* rp = (const float2*)(st + (size_t)row * SD);
        float2 x = rp[t];
        __shared__ float red2[8];
        __shared__ float z_mu, z_rstd;
        float p = x.x + x.y;
        #pragma unroll
        for (int o = 16; o; o >>= 1) p += __shfl_xor_sync(~0u, p, o);
        if ((t & 31) == 0) red2[t >> 5] = p;
        __syncthreads();
        if (t == 0) { float s = 0;
            #pragma unroll
            for (int i = 0; i < 8; i++) s += red2[i]; z_mu = s * (1.f / SD); }
        __syncthreads();
        float mu = z_mu;
        float d0 = x.x - mu, d1 = x.y - mu;
        p = d0*d0 + d1*d1;
        #pragma unroll
        for (int o = 16; o; o >>= 1) p += __shfl_xor_sync(~0u, p, o);
        if ((t & 31) == 0) red2[t >> 5] = p;
        __syncthreads();
        if (t == 0) { float s = 0;
            #pragma unroll
            for (int i = 0; i < 8; i++) s += red2[i]; z_rstd = rsqrtf(s * (1.f / SD) + 1e-5f); }
        __syncthreads();
        float r = z_rstd;
        int c = t * 2;
        float2 y;
        y.x = d0 * r * lnsg[c]     + lnsb[c];
        y.y = d1 * r * lnsg[c + 1] + lnsb[c + 1];
        ((float2*)(g_sn + (size_t)row * SD))[t] = y;
    } else {
        int idx = bid - NB * NN;             // 0..31
        int p = (idx & 1) * 256 + t;
        int k0 = (idx >> 1) * 64;
        float acc = 0.f;
        #pragma unroll 8
        for (int kk = 0; kk < 64; kk++) acc += bt[k0 + kk] * Wq[(size_t)(k0 + kk) * PD + p];
        g_qpart[(idx >> 1) * PD + p] = acc;
    }
}

// ============================================================================
// prepB: kproj (32 blocks) | qreduce (2 blocks)
// ============================================================================
__global__ void prepB_kernel(const float* __restrict__ Wk, const float* __restrict__ bk,
                             const float* __restrict__ bq) {
    int bid = blockIdx.x, t = threadIdx.x;
    if (bid < 32) {
        int r0 = (bid & 7) * 64, p0 = (bid >> 3) * 128;
        __shared__ float sSn[64 * 33];
        __shared__ float sWk[32 * 128];
        int tr = t >> 4, tp = t & 15;
        float acc[4][8];
        #pragma unroll
        for (int i = 0; i < 4; i++)
            #pragma unroll
            for (int j = 0; j < 8; j++) acc[i][j] = 0.f;
        for (int c0 = 0; c0 < SD; c0 += 32) {
            for (int idx = t; idx < 64 * 32; idx += 256) {
                int rr = idx >> 5, cc = idx & 31;
                sSn[rr * 33 + cc] = g_sn[(size_t)(r0 + rr) * SD + c0 + cc];
            }
            for (int idx = t; idx < 32 * 128; idx += 256) {
                int cc = idx >> 7, pp = idx & 127;
                sWk[cc * 128 + pp] = Wk[(size_t)(c0 + cc) * PD + p0 + pp];
            }
            __syncthreads();
            for (int cc = 0; cc < 32; cc++) {
                float a0 = sSn[(tr*4+0)*33+cc], a1 = sSn[(tr*4+1)*33+cc];
                float a2 = sSn[(tr*4+2)*33+cc], a3 = sSn[(tr*4+3)*33+cc];
                #pragma unroll
                for (int pp = 0; pp < 8; pp++) {
                    float w = sWk[cc * 128 + tp * 8 + pp];
                    acc[0][pp] += a0 * w; acc[1][pp] += a1 * w;
                    acc[2][pp] += a2 * w; acc[3][pp] += a3 * w;
                }
            }
            __syncthreads();
        }
        #pragma unroll
        for (int rr = 0; rr < 4; rr++)
            #pragma unroll
            for (int pp = 0; pp < 8; pp++) {
                int p = p0 + tp * 8 + pp;
                g_kfull[(size_t)(r0 + tr*4 + rr) * PD + p] = acc[rr][pp] + bk[p];
            }
    } else {
        int p = (bid - 32) * 256 + t;
        float s = bq[p];
        #pragma unroll
        for (int j = 0; j < 16; j++) s += g_qpart[j * PD + p];
        g_qconst[p] = s;
    }
}

// ============================================================================
// prepC: cbuild (256 blocks) | biasv (8 blocks)
// ============================================================================
__global__ void prepC_kernel(const float* __restrict__ Wq, const float* __restrict__ gt,
                             const float* __restrict__ temp) {
    int bid = blockIdx.x, t = threadIdx.x;
    if (bid < 256) {
        int kt = bid & 15, h = (bid >> 4) & 3, b = bid >> 6;
        int k0 = kt * 64;
        float invt = 1.f / fmaxf(temp[0], 0.1f);
        __shared__ float sKp[128 * 33];
        __shared__ float sWg[64 * 33];
        int k = t >> 2, nq = t & 3;
        float acc[32];
        #pragma unroll
        for (int i = 0; i < 32; i++) acc[i] = 0.f;
        for (int dc = 0; dc < HD; dc += 32) {
            for (int idx = t; idx < 128 * 32; idx += 256) {
                int n = idx >> 5, dd = idx & 31;
                sKp[n * 33 + dd] = g_kfull[((size_t)(b * NN + n)) * PD + h * HD + dc + dd] * invt;
            }
            for (int idx = t; idx < 64 * 32; idx += 256) {
                int kk2 = idx >> 5, dd = idx & 31;
                sWg[kk2 * 33 + dd] = Wq[(size_t)(k0 + kk2) * PD + h * HD + dc + dd] * gt[k0 + kk2];
            }
            __syncthreads();
            for (int dd = 0; dd < 32; dd++) {
                float a = sWg[k * 33 + dd];
                #pragma unroll
                for (int nn = 0; nn < 32; nn++)
                    acc[nn] += a * sKp[(nn * 4 + nq) * 33 + dd];
            }
            __syncthreads();
        }
        size_t base = ((size_t)(b * NH + h) * TD + k0 + k) * HD;
        #pragma unroll
        for (int nn = 0; nn < 32; nn++) {
            int n = nn * 4 + nq;
            float v = acc[nn];
            __nv_bfloat16 hi = __float2bfloat16(v);
            g_Chi[base + n] = hi;
            g_Clo[base + n] = __float2bfloat16(v - __bfloat162float(hi));
        }
    } else {
        int gi = (bid - 256) * 256 + t;   // 0..2047
        int b = gi >> 9, r = gi & 511;
        int h = r >> 7, n = r & 127;
        float invt = 1.f / fmaxf(temp[0], 0.1f);
        const float* kp = &g_kfull[((size_t)(b * NN + n)) * PD + h * HD];
        const float* qc = &g_qconst[h * HD];
        float acc = 0.f;
        for (int d = 0; d < HD; d++) acc += qc[d] * kp[d];
        g_biasv[b * PD + r] = acc * invt;
    }
}

// ============================================================================
// tokln: token LN -> split bf16 hi/lo + passthrough, warp-per-row (overlapped)
// ============================================================================
__global__ void tokln_kernel(const float* __restrict__ tok, float* __restrict__ out_tok) {
    int t = threadIdx.x, w = t >> 5, l = t & 31;
    int row = blockIdx.x * 8 + w;
    const float4* rp = (const float4*)(tok + (size_t)row * TD);
    float4* wp = (float4*)(out_tok + (size_t)row * TD);
    float4 x[8];
    #pragma unroll
    for (int j = 0; j < 8; j++) x[j] = rp[j * 32 + l];
    #pragma unroll
    for (int j = 0; j < 8; j++) wp[j * 32 + l] = x[j];   // passthrough
    float p = 0.f;
    #pragma unroll
    for (int j = 0; j < 8; j++) p += (x[j].x + x[j].y) + (x[j].z + x[j].w);
    #pragma unroll
    for (int o = 16; o; o >>= 1) p += __shfl_xor_sync(~0u, p, o);
    float mu = p * (1.f / TD);
    float v = 0.f;
    #pragma unroll
    for (int j = 0; j < 8; j++) {
        float a = x[j].x - mu, b = x[j].y - mu, c = x[j].z - mu, d = x[j].w - mu;
        v += a*a + b*b + c*c + d*d;
    }
    #pragma unroll
    for (int o = 16; o; o >>= 1) v += __shfl_xor_sync(~0u, v, o);
    float r = rsqrtf(v * (1.f / TD) + 1e-5f);
    #pragma unroll
    for (int j = 0; j < 8; j++) {
        float z0 = (x[j].x - mu) * r, z1 = (x[j].y - mu) * r;
        float z2 = (x[j].z - mu) * r, z3 = (x[j].w - mu) * r;
        union { __nv_bfloat16 b[4]; uint2 u; } hz, lz;
        hz.b[0] = __float2bfloat16(z0); lz.b[0] = __float2bfloat16(z0 - __bfloat162float(hz.b[0]));
        hz.b[1] = __float2bfloat16(z1); lz.b[1] = __float2bfloat16(z1 - __bfloat162float(hz.b[1]));
        hz.b[2] = __float2bfloat16(z2); lz.b[2] = __float2bfloat16(z2 - __bfloat162float(hz.b[2]));
        hz.b[3] = __float2bfloat16(z3); lz.b[3] = __float2bfloat16(z3 - __bfloat162float(hz.b[3]));
        int idx = (j * 32 + l) * 4;
        *reinterpret_cast<uint2*>(&g_Ahi[(size_t)row * TD + idx]) = hz.u;
        *reinterpret_cast<uint2*>(&g_Alo[(size_t)row * TD + idx]) = lz.u;
    }
}

// ============================================================================
// main GEMM + per-head softmax (R7/R9 proven: BK=64, 2-stage, 96KB smem)
// grid (stile=64, h=4, b=4), block 256 (8 warps: 4m x 2n), BM=64 BN=128
// ============================================================================
__global__ void __launch_bounds__(256, 2) main_kernel() {
    extern __shared__ char smem[];
    int stile = blockIdx.x, h = blockIdx.y, b = blockIdx.z;
    int t = threadIdx.x, l = t & 31, w = t >> 5;
    int wm = w >> 1, wn = w & 1;
    const int STG = 49152;   // per-stage: Ahi 8K | Alo 8K | Chi 16K | Clo 16K
    __shared__ float sBias[128];
    __shared__ float sMax[64][2], sSum[64][2];
    if (t < 128) sBias[t] = g_biasv[b * PD + h * HD + t];

    const __nv_bfloat16* gA_hi = g_Ahi + ((size_t)(b * NS + stile * 64)) * TD;
    const __nv_bfloat16* gA_lo = g_Alo + ((size_t)(b * NS + stile * 64)) * TD;
    const __nv_bfloat16* gC_hi = g_Chi + (size_t)(b * NH + h) * TD * HD;
    const __nv_bfloat16* gC_lo = g_Clo + (size_t)(b * NH + h) * TD * HD;

    auto loadStage = [&](int s, int kk) {
        char* base = smem + s * STG;
        #pragma unroll
        for (int i = 0; i < 2; i++) {
            int cid = t + i * 256, m = cid >> 3, c = cid & 7;
            int cc = c ^ (m & 7);
            cpa16(base + m * 128 + cc * 16,        gA_hi + (size_t)m * TD + kk + c * 8);
            cpa16(base + 8192 + m * 128 + cc * 16, gA_lo + (size_t)m * TD + kk + c * 8);
        }
        #pragma unroll
        for (int i = 0; i < 4; i++) {
            int cid = t + i * 256, k = cid >> 4, c = cid & 15;
            int cc = (c & 8) | ((c & 7) ^ (k & 7));
            cpa16(base + 16384 + k * 256 + cc * 16, gC_hi + (size_t)(kk + k) * HD + c * 8);
            cpa16(base + 32768 + k * 256 + cc * 16, gC_lo + (size_t)(kk + k) * HD + c * 8);
        }
    };

    float acc[8][4];
    #pragma unroll
    for (int j = 0; j < 8; j++)
        #pragma unroll
        for (int q = 0; q < 4; q++) acc[j][q] = 0.f;

    int mA = wm * 16 + (l & 15);
    int selA = l >> 4;
    int aRowOff = mA * 128, aX = mA & 7;
    int kb = ((l >> 3) & 1) * 8 + (l & 7);
    int cpB[4];
    #pragma unroll
    for (int q = 0; q < 4; q++) {
        int c = wn * 8 + q * 2 + (l >> 4);
        cpB[q] = (c & 8) | ((c & 7) ^ (l & 7));
    }

    loadStage(0, 0);
    CP_COMMIT();

    for (int it = 0; it < 16; ++it) {
        if (it + 1 < 16) loadStage((it + 1) & 1, (it + 1) * 64);
        CP_COMMIT();
        CP_WAIT1();
        __syncthreads();
        char* base = smem + (it & 1) * STG;
        #pragma unroll
        for (int ks = 0; ks < 4; ++ks) {
            unsigned ahi[4], alo[4];
            int aoff = aRowOff + (((ks * 2 + selA) ^ aX) << 4);
            ldsm4(ahi, base + aoff);
            ldsm4(alo, base + 8192 + aoff);
            unsigned bhi[16], blo[16];
            #pragma unroll
            for (int q = 0; q < 4; q++) {
                int off = (ks * 16 + kb) * 256 + cpB[q] * 16;
                ldsm4t(&bhi[q * 4], base + 16384 + off);
                ldsm4t(&blo[q * 4], base + 32768 + off);
            }
            #pragma unroll
            for (int j = 0; j < 8; j++) {
                mma_bf16(acc[j], ahi, &bhi[j * 2]);
                mma_bf16(acc[j], ahi, &blo[j * 2]);
                mma_bf16(acc[j], alo, &bhi[j * 2]);
            }
        }
        __syncthreads();
    }

    // ---- epilogue: +bias, per-head softmax over n (BN=128 = all states) ----
    int r0 = wm * 16 + (l >> 2);
    int cb = wn * 64 + (l & 3) * 2;
    #pragma unroll
    for (int j = 0; j < 8; j++) {
        float b0 = sBias[cb + j * 8], b1 = sBias[cb + j * 8 + 1];
        acc[j][0] += b0; acc[j][1] += b1; acc[j][2] += b0; acc[j][3] += b1;
    }
    float mx0 = -1e30f, mx8 = -1e30f;
    #pragma unroll
    for (int j = 0; j < 8; j++) {
        mx0 = fmaxf(mx0, fmaxf(acc[j][0], acc[j][1]));
        mx8 = fmaxf(mx8, fmaxf(acc[j][2], acc[j][3]));
    }
    mx0 = fmaxf(mx0, __shfl_xor_sync(~0u, mx0, 1));
    mx0 = fmaxf(mx0, __shfl_xor_sync(~0u, mx0, 2));
    mx8 = fmaxf(mx8, __shfl_xor_sync(~0u, mx8, 1));
    mx8 = fmaxf(mx8, __shfl_xor_sync(~0u, mx8, 2));
    if ((l & 3) == 0) { sMax[r0][wn] = mx0; sMax[r0 + 8][wn] = mx8; }
    __syncthreads();
    float M0 = fmaxf(sMax[r0][0], sMax[r0][1]);
    float M8 = fmaxf(sMax[r0 + 8][0], sMax[r0 + 8][1]);
    float s0 = 0.f, s8 = 0.f;
    #pragma unroll
    for (int j = 0; j < 8; j++) {
        acc[j][0] = __expf(acc[j][0] - M0); s0 += acc[j][0];
        acc[j][1] = __expf(acc[j][1] - M0); s0 += acc[j][1];
        acc[j][2] = __expf(acc[j][2] - M8); s8 += acc[j][2];
        acc[j][3] = __expf(acc[j][3] - M8); s8 += acc[j][3];
    }
    s0 += __shfl_xor_sync(~0u, s0, 1); s0 += __shfl_xor_sync(~0u, s0, 2);
    s8 += __shfl_xor_sync(~0u, s8, 1); s8 += __shfl_xor_sync(~0u, s8, 2);
    if ((l & 3) == 0) { sSum[r0][wn] = s0; sSum[r0 + 8][wn] = s8; }
    __syncthreads();
    float inv0 = 1.f / (sSum[r0][0] + sSum[r0][1]);
    float inv8 = 1.f / (sSum[r0 + 8][0] + sSum[r0 + 8][1]);
    __half* wout = g_w + ((size_t)(b * NH + h) * NS + stile * 64) * NN;
    #pragma unroll
    for (int j = 0; j < 8; j++) {
        *(__half2*)(wout + (size_t)r0 * NN + cb + j * 8) =
            __floats2half2_rn(acc[j][0] * inv0, acc[j][1] * inv0);
        *(__half2*)(wout + (size_t)(r0 + 8) * NN + cb + j * 8) =
            __floats2half2_rn(acc[j][2] * inv8, acc[j][3] * inv8);
    }
}

// ============================================================================
// meanent: head-mean + entropy partials (warp-per-row, fp16 reads, no atomics)
// ============================================================================
__global__ void meanent_kernel(float* __restrict__ out_rout) {
    int t = threadIdx.x, w = t >> 5, l = t & 31;
    int row = blockIdx.x * 8 + w;             // row = b*4096+s
    int b = row >> 12, s = row & 4095;
    size_t hs = (size_t)NS * NN;
    size_t base = ((size_t)(b * NH) * NS + s) * NN + l * 4;
    float a0 = 0.f, a1 = 0.f, a2 = 0.f, a3 = 0.f;
    #pragma unroll
    for (int h = 0; h < NH; h++) {
        const __half2* p = (const __half2*)(g_w + base + h * hs);
        float2 x = __half22float2(p[0]);
        float2 y = __half22float2(p[1]);
        a0 += x.x; a1 += x.y; a2 += y.x; a3 += y.y;
    }
    float4 v = make_float4(a0 * 0.25f, a1 * 0.25f, a2 * 0.25f, a3 * 0.25f);
    *(float4*)(out_rout + (size_t)row * NN + l * 4) = v;
    float c = v.x * __logf(v.x + 1e-8f) + v.y * __logf(v.y + 1e-8f)
            + v.z * __logf(v.z + 1e-8f) + v.w * __logf(v.w + 1e-8f);
    #pragma unroll
    for (int o = 16; o; o >>= 1) c += __shfl_xor_sync(~0u, c, o);
    __shared__ float red[8];
    if (l == 0) red[w] = c;
    __syncthreads();
    if (t == 0) {
        float s2 = 0.f;
        #pragma unroll
        for (int i = 0; i < 8; i++) s2 += red[i];
        g_entpart[blockIdx.x] = s2;
    }
}

// ============================================================================
// fin: final reduce of 2048 partials -> loss scalar
// ============================================================================
__global__ void fin_kernel(float* __restrict__ out) {
    int t = threadIdx.x;
    float s = 0.f;
    #pragma unroll
    for (int i = 0; i < 8; i++) s += g_entpart[i * 256 + t];
    #pragma unroll
    for (int o = 16; o; o >>= 1) s += __shfl_xor_sync(~0u, s, o);
    __shared__ float red[8];
    if ((t & 31) == 0) red[t >> 5] = s;
    __syncthreads();
    if (t == 0) {
        float tot = 0.f;
        #pragma unroll
        for (int i = 0; i < 8; i++) tot += red[i];
        out[0] = tot * (0.01f / (float)NTOK);
    }
}

// ---------------- launch: fork prep chain onto side stream, overlap tokln ----
extern "C" void kernel_launch(void* const* d_in, const int* in_sizes, int n_in,
                              void* d_out, int out_size) {
    (void)in_sizes; (void)n_in; (void)out_size;
    const float* tokens = (const float*)d_in[0];
    const float* states = (const float*)d_in[1];
    const float* ln_t_g = (const float*)d_in[2];
    const float* ln_t_b = (const float*)d_in[3];
    const float* ln_s_g = (const float*)d_in[4];
    const float* ln_s_b = (const float*)d_in[5];
    const float* Wq     = (const float*)d_in[6];
    const float* bq     = (const float*)d_in[7];
    const float* Wk     = (const float*)d_in[8];
    const float* bk     = (const float*)d_in[9];
    const float* temp   = (const float*)d_in[10];
    float* out = (float*)d_out;

    static cudaStream_t s2 = nullptr;
    static cudaEvent_t evF = nullptr, evJ = nullptr;
    if (s2 == nullptr) {                      // created on the (uncaptured) first call
        cudaStreamCreateWithFlags(&s2, cudaStreamNonBlocking);
        cudaEventCreateWithFlags(&evF, cudaEventDisableTiming);
        cudaEventCreateWithFlags(&evJ, cudaEventDisableTiming);
        cudaFuncSetAttribute(main_kernel, cudaFuncAttributeMaxDynamicSharedMemorySize, 98304);
    }
    cudaFuncSetAttribute(main_kernel, cudaFuncAttributeMaxDynamicSharedMemorySize, 98304);

    // fork: side stream runs the small prep chain while stream 0 runs tokln
    cudaEventRecord(evF, 0);
    cudaStreamWaitEvent(s2, evF, 0);

    prepA_kernel<<<NB * NN + 32, 256, 0, s2>>>(states, ln_s_g, ln_s_b, Wq, ln_t_b);
    tokln_kernel<<<2048, 256>>>(tokens, out);            // overlaps with prep chain
    prepB_kernel<<<34, 256, 0, s2>>>(Wk, bk, bq);
    prepC_kernel<<<264, 256, 0, s2>>>(Wq, ln_t_g, temp);

    // join: main needs both branches
    cudaEventRecord(evJ, s2);
    cudaStreamWaitEvent(0, evJ, 0);

    main_kernel<<<dim3(64, 4, 4), 256, 98304>>>();
    meanent_kernel<<<2048, 256>>>(out + (size_t)NTOK * TD);
    fin_kernel<<<1, 256>>>(out + (size_t)NTOK * TD + (size_t)NTOK * NN);
}

// round 12
// speedup vs baseline: 1.3223x; 1.3223x over previous
#include <cuda_runtime.h>
#include <cuda_bf16.h>
#include <cuda_fp16.h>
#include <math.h>

#define NB 4
#define NS 4096
#define NN 128
#define TD 1024
#define SD 512
#define PD 512
#define NH 4
#define HD 128
#define NTOK (NB*NS)

// ---------------- static device scratch (no runtime alloc allowed) ----------
__device__ __align__(16) __nv_bfloat16 g_Ahi[NTOK*TD];        // 32 MB
__device__ __align__(16) __nv_bfloat16 g_Alo[NTOK*TD];        // 32 MB
__device__ __align__(16) float g_sn[NB*NN*SD];                // 1 MB
__device__ __align__(16) float g_kfull[NB*NN*PD];             // 1 MB
__device__ float g_qpart[16*PD];
__device__ float g_qconst[PD];
__device__ float g_biasv[NB*PD];
__device__ __align__(16) __nv_bfloat16 g_Chi[NB*NH*TD*HD];    // 4 MB  [b][h][k][n]
__device__ __align__(16) __nv_bfloat16 g_Clo[NB*NH*TD*HD];    // 4 MB
__device__ __align__(16) __half g_w[(size_t)NB*NH*NS*NN];     // 16 MB (fp16 weights)
__device__ float g_entpart[2048];

// ---------------- PTX helpers ----------------------------------------------
__device__ __forceinline__ void ldsm4(unsigned r[4], const void* p) {
    unsigned a = (unsigned)__cvta_generic_to_shared(p);
    asm volatile("ldmatrix.sync.aligned.m8n8.x4.shared.b16 {%0,%1,%2,%3}, [%4];"
                 : "=r"(r[0]), "=r"(r[1]), "=r"(r[2]), "=r"(r[3]) : "r"(a));
}
__device__ __forceinline__ void ldsm4t(unsigned* r, const void* p) {
    unsigned a = (unsigned)__cvta_generic_to_shared(p);
    asm volatile("ldmatrix.sync.aligned.m8n8.x4.trans.shared.b16 {%0,%1,%2,%3}, [%4];"
                 : "=r"(r[0]), "=r"(r[1]), "=r"(r[2]), "=r"(r[3]) : "r"(a));
}
__device__ __forceinline__ void mma_bf16(float c[4], const unsigned a[4], const unsigned b[2]) {
    asm volatile("mma.sync.aligned.m16n8k16.row.col.f32.bf16.bf16.f32 "
                 "{%0,%1,%2,%3},{%4,%5,%6,%7},{%8,%9},{%0,%1,%2,%3};"
                 : "+f"(c[0]), "+f"(c[1]), "+f"(c[2]), "+f"(c[3])
                 : "r"(a[0]), "r"(a[1]), "r"(a[2]), "r"(a[3]), "r"(b[0]), "r"(b[1]));
}
__device__ __forceinline__ void cpa16(void* s, const void* g) {
    unsigned sa = (unsigned)__cvta_generic_to_shared(s);
    asm volatile("cp.async.cg.shared.global [%0],[%1],16;" :: "r"(sa), "l"(g) : "memory");
}
#define CP_COMMIT() asm volatile("cp.async.commit_group;" ::: "memory")
#define CP_WAIT1()  asm volatile("cp.async.wait_group 1;"  ::: "memory")

// ============================================================================
// L1 prepA: state LN (512 blocks) | qconst split-K partials (32 blocks)
// ============================================================================
__global__ void prepA_kernel(const float* __restrict__ st,
                             const float* __restrict__ lnsg, const float* __restrict__ lnsb,
                             const float* __restrict__ Wq, const float* __restrict__ bt) {
    int bid = blockIdx.x, t = threadIdx.x;
    if (bid < NB * NN) {
        int row = bid;
        const float2* rp = (const float2*)(st + (size_t)row * SD);
        float2 x = rp[t];
        __shared__ float red2[8];
        __shared__ float z_mu, z_rstd;
        float p = x.x + x.y;
        #pragma unroll
        for (int o = 16; o; o >>= 1) p += __shfl_xor_sync(~0u, p, o);
        if ((t & 31) == 0) red2[t >> 5] = p;
        __syncthreads();
        if (t == 0) { float s = 0;
            #pragma unroll
            for (int i = 0; i < 8; i++) s += red2[i]; z_mu = s * (1.f / SD); }
        __syncthreads();
        float mu = z_mu;
        float d0 = x.x - mu, d1 = x.y - mu;
        p = d0*d0 + d1*d1;
        #pragma unroll
        for (int o = 16; o; o >>= 1) p += __shfl_xor_sync(~0u, p, o);
        if ((t & 31) == 0) red2[t >> 5] = p;
        __syncthreads();
        if (t == 0) { float s = 0;
            #pragma unroll
            for (int i = 0; i < 8; i++) s += red2[i]; z_rstd = rsqrtf(s * (1.f / SD) + 1e-5f); }
        __syncthreads();
        float r = z_rstd;
        int c = t * 2;
        float2 y;
        y.x = d0 * r * lnsg[c]     + lnsb[c];
        y.y = d1 * r * lnsg[c + 1] + lnsb[c + 1];
        ((float2*)(g_sn + (size_t)row * SD))[t] = y;
    } else {
        int idx = bid - NB * NN;             // 0..31
        int p = (idx & 1) * 256 + t;
        int k0 = (idx >> 1) * 64;
        float acc = 0.f;
        #pragma unroll 8
        for (int kk = 0; kk < 64; kk++) acc += bt[k0 + kk] * Wq[(size_t)(k0 + kk) * PD + p];
        g_qpart[(idx >> 1) * PD + p] = acc;
    }
}

// ============================================================================
// L2 prepB: kproj (32 blocks) | qreduce (2 blocks)
// ============================================================================
__global__ void prepB_kernel(const float* __restrict__ Wk, const float* __restrict__ bk,
                             const float* __restrict__ bq) {
    int bid = blockIdx.x, t = threadIdx.x;
    if (bid < 32) {
        int r0 = (bid & 7) * 64, p0 = (bid >> 3) * 128;
        __shared__ float sSn[64 * 33];
        __shared__ float sWk[32 * 128];
        int tr = t >> 4, tp = t & 15;
        float acc[4][8];
        #pragma unroll
        for (int i = 0; i < 4; i++)
            #pragma unroll
            for (int j = 0; j < 8; j++) acc[i][j] = 0.f;
        for (int c0 = 0; c0 < SD; c0 += 32) {
            for (int idx = t; idx < 64 * 32; idx += 256) {
                int rr = idx >> 5, cc = idx & 31;
                sSn[rr * 33 + cc] = g_sn[(size_t)(r0 + rr) * SD + c0 + cc];
            }
            for (int idx = t; idx < 32 * 128; idx += 256) {
                int cc = idx >> 7, pp = idx & 127;
                sWk[cc * 128 + pp] = Wk[(size_t)(c0 + cc) * PD + p0 + pp];
            }
            __syncthreads();
            for (int cc = 0; cc < 32; cc++) {
                float a0 = sSn[(tr*4+0)*33+cc], a1 = sSn[(tr*4+1)*33+cc];
                float a2 = sSn[(tr*4+2)*33+cc], a3 = sSn[(tr*4+3)*33+cc];
                #pragma unroll
                for (int pp = 0; pp < 8; pp++) {
                    float w = sWk[cc * 128 + tp * 8 + pp];
                    acc[0][pp] += a0 * w; acc[1][pp] += a1 * w;
                    acc[2][pp] += a2 * w; acc[3][pp] += a3 * w;
                }
            }
            __syncthreads();
        }
        #pragma unroll
        for (int rr = 0; rr < 4; rr++)
            #pragma unroll
            for (int pp = 0; pp < 8; pp++) {
                int p = p0 + tp * 8 + pp;
                g_kfull[(size_t)(r0 + tr*4 + rr) * PD + p] = acc[rr][pp] + bk[p];
            }
    } else {
        int p = (bid - 32) * 256 + t;
        float s = bq[p];
        #pragma unroll
        for (int j = 0; j < 16; j++) s += g_qpart[j * PD + p];
        g_qconst[p] = s;
    }
}

// ============================================================================
// L3 tokln: token LN -> split bf16 hi/lo + passthrough, warp-per-row
// ============================================================================
__global__ void tokln_kernel(const float* __restrict__ tok, float* __restrict__ out_tok) {
    int t = threadIdx.x, w = t >> 5, l = t & 31;
    int row = blockIdx.x * 8 + w;
    const float4* rp = (const float4*)(tok + (size_t)row * TD);
    float4* wp = (float4*)(out_tok + (size_t)row * TD);
    float4 x[8];
    #pragma unroll
    for (int j = 0; j < 8; j++) x[j] = rp[j * 32 + l];
    #pragma unroll
    for (int j = 0; j < 8; j++) wp[j * 32 + l] = x[j];   // passthrough
    float p = 0.f;
    #pragma unroll
    for (int j = 0; j < 8; j++) p += (x[j].x + x[j].y) + (x[j].z + x[j].w);
    #pragma unroll
    for (int o = 16; o; o >>= 1) p += __shfl_xor_sync(~0u, p, o);
    float mu = p * (1.f / TD);
    float v = 0.f;
    #pragma unroll
    for (int j = 0; j < 8; j++) {
        float a = x[j].x - mu, b = x[j].y - mu, c = x[j].z - mu, d = x[j].w - mu;
        v += a*a + b*b + c*c + d*d;
    }
    #pragma unroll
    for (int o = 16; o; o >>= 1) v += __shfl_xor_sync(~0u, v, o);
    float r = rsqrtf(v * (1.f / TD) + 1e-5f);
    #pragma unroll
    for (int j = 0; j < 8; j++) {
        float z0 = (x[j].x - mu) * r, z1 = (x[j].y - mu) * r;
        float z2 = (x[j].z - mu) * r, z3 = (x[j].w - mu) * r;
        union { __nv_bfloat16 b[4]; uint2 u; } hz, lz;
        hz.b[0] = __float2bfloat16(z0); lz.b[0] = __float2bfloat16(z0 - __bfloat162float(hz.b[0]));
        hz.b[1] = __float2bfloat16(z1); lz.b[1] = __float2bfloat16(z1 - __bfloat162float(hz.b[1]));
        hz.b[2] = __float2bfloat16(z2); lz.b[2] = __float2bfloat16(z2 - __bfloat162float(hz.b[2]));
        hz.b[3] = __float2bfloat16(z3); lz.b[3] = __float2bfloat16(z3 - __bfloat162float(hz.b[3]));
        int idx = (j * 32 + l) * 4;
        *reinterpret_cast<uint2*>(&g_Ahi[(size_t)row * TD + idx]) = hz.u;
        *reinterpret_cast<uint2*>(&g_Alo[(size_t)row * TD + idx]) = lz.u;
    }
}

// ============================================================================
// L4 prepC (PROFILED): cbuild 4kx8n register-blocked (256 blocks) | biasv (8)
// per (kt,h,b) block: C tile 64k x 128n over d=128.  12 LDS per 32 FMA.
// ============================================================================
__global__ void prepC_kernel(const float* __restrict__ Wq, const float* __restrict__ gt,
                             const float* __restrict__ temp) {
    int bid = blockIdx.x, t = threadIdx.x;
    if (bid < 256) {
        int kt = bid & 15, h = (bid >> 4) & 3, b = bid >> 6;
        int k0 = kt * 64;
        float invt = 1.f / fmaxf(temp[0], 0.1f);
        __shared__ float sWg[64 * 33];    // [k][dd] pad 33 -> bcast reads
        __shared__ float sKp[32 * 133];   // [dd][n] pad 133 -> conflict-free
        int tr = t >> 4, tp = t & 15;
        float acc[4][8];
        #pragma unroll
        for (int i = 0; i < 4; i++)
            #pragma unroll
            for (int j = 0; j < 8; j++) acc[i][j] = 0.f;
        int dd0 = t & 31, grp = t >> 5;
        for (int dc = 0; dc < HD; dc += 32) {
            #pragma unroll
            for (int kk = grp; kk < 64; kk += 8)
                sWg[kk * 33 + dd0] = Wq[(size_t)(k0 + kk) * PD + h * HD + dc + dd0] * gt[k0 + kk];
            #pragma unroll
            for (int n = grp; n < 128; n += 8)
                sKp[dd0 * 133 + n] = g_kfull[((size_t)(b * NN + n)) * PD + h * HD + dc + dd0] * invt;
            __syncthreads();
            #pragma unroll
            for (int dd = 0; dd < 32; dd++) {
                float a0 = sWg[(tr * 4 + 0) * 33 + dd];
                float a1 = sWg[(tr * 4 + 1) * 33 + dd];
                float a2 = sWg[(tr * 4 + 2) * 33 + dd];
                float a3 = sWg[(tr * 4 + 3) * 33 + dd];
                #pragma unroll
                for (int pp = 0; pp < 8; pp++) {
                    float w = sKp[dd * 133 + tp + 16 * pp];
                    acc[0][pp] += a0 * w; acc[1][pp] += a1 * w;
                    acc[2][pp] += a2 * w; acc[3][pp] += a3 * w;
                }
            }
            __syncthreads();
        }
        #pragma unroll
        for (int i = 0; i < 4; i++) {
            int k = k0 + tr * 4 + i;
            size_t rowb = ((size_t)(b * NH + h) * TD + k) * HD;
            #pragma unroll
            for (int pp = 0; pp < 8; pp++) {
                int n = tp + 16 * pp;
                float v = acc[i][pp];
                __nv_bfloat16 hi = __float2bfloat16(v);
                g_Chi[rowb + n] = hi;
                g_Clo[rowb + n] = __float2bfloat16(v - __bfloat162float(hi));
            }
        }
    } else {
        int gi = (bid - 256) * 256 + t;   // 0..2047
        int b = gi >> 9, r = gi & 511;
        int h = r >> 7, n = r & 127;
        float invt = 1.f / fmaxf(temp[0], 0.1f);
        const float* kp = &g_kfull[((size_t)(b * NN + n)) * PD + h * HD];
        const float* qc = &g_qconst[h * HD];
        float acc = 0.f;
        for (int d = 0; d < HD; d++) acc += qc[d] * kp[d];
        g_biasv[b * PD + r] = acc * invt;
    }
}

// ============================================================================
// L5 main: GEMM + per-head softmax (R7/R9 proven: BK=64, 2-stage, 96KB smem)
// grid (stile=64, h=4, b=4), block 256 (8 warps: 4m x 2n), BM=64 BN=128
// ============================================================================
__global__ void __launch_bounds__(256, 2) main_kernel() {
    extern __shared__ char smem[];
    int stile = blockIdx.x, h = blockIdx.y, b = blockIdx.z;
    int t = threadIdx.x, l = t & 31, w = t >> 5;
    int wm = w >> 1, wn = w & 1;
    const int STG = 49152;   // per-stage: Ahi 8K | Alo 8K | Chi 16K | Clo 16K
    __shared__ float sBias[128];
    __shared__ float sMax[64][2], sSum[64][2];
    if (t < 128) sBias[t] = g_biasv[b * PD + h * HD + t];

    const __nv_bfloat16* gA_hi = g_Ahi + ((size_t)(b * NS + stile * 64)) * TD;
    const __nv_bfloat16* gA_lo = g_Alo + ((size_t)(b * NS + stile * 64)) * TD;
    const __nv_bfloat16* gC_hi = g_Chi + (size_t)(b * NH + h) * TD * HD;
    const __nv_bfloat16* gC_lo = g_Clo + (size_t)(b * NH + h) * TD * HD;

    auto loadStage = [&](int s, int kk) {
        char* base = smem + s * STG;
        #pragma unroll
        for (int i = 0; i < 2; i++) {
            int cid = t + i * 256, m = cid >> 3, c = cid & 7;
            int cc = c ^ (m & 7);
            cpa16(base + m * 128 + cc * 16,        gA_hi + (size_t)m * TD + kk + c * 8);
            cpa16(base + 8192 + m * 128 + cc * 16, gA_lo + (size_t)m * TD + kk + c * 8);
        }
        #pragma unroll
        for (int i = 0; i < 4; i++) {
            int cid = t + i * 256, k = cid >> 4, c = cid & 15;
            int cc = (c & 8) | ((c & 7) ^ (k & 7));
            cpa16(base + 16384 + k * 256 + cc * 16, gC_hi + (size_t)(kk + k) * HD + c * 8);
            cpa16(base + 32768 + k * 256 + cc * 16, gC_lo + (size_t)(kk + k) * HD + c * 8);
        }
    };

    float acc[8][4];
    #pragma unroll
    for (int j = 0; j < 8; j++)
        #pragma unroll
        for (int q = 0; q < 4; q++) acc[j][q] = 0.f;

    int mA = wm * 16 + (l & 15);
    int selA = l >> 4;
    int aRowOff = mA * 128, aX = mA & 7;
    int kb = ((l >> 3) & 1) * 8 + (l & 7);
    int cpB[4];
    #pragma unroll
    for (int q = 0; q < 4; q++) {
        int c = wn * 8 + q * 2 + (l >> 4);
        cpB[q] = (c & 8) | ((c & 7) ^ (l & 7));
    }

    loadStage(0, 0);
    CP_COMMIT();

    for (int it = 0; it < 16; ++it) {
        if (it + 1 < 16) loadStage((it + 1) & 1, (it + 1) * 64);
        CP_COMMIT();
        CP_WAIT1();
        __syncthreads();
        char* base = smem + (it & 1) * STG;
        #pragma unroll
        for (int ks = 0; ks < 4; ++ks) {
            unsigned ahi[4], alo[4];
            int aoff = aRowOff + (((ks * 2 + selA) ^ aX) << 4);
            ldsm4(ahi, base + aoff);
            ldsm4(alo, base + 8192 + aoff);
            unsigned bhi[16], blo[16];
            #pragma unroll
            for (int q = 0; q < 4; q++) {
                int off = (ks * 16 + kb) * 256 + cpB[q] * 16;
                ldsm4t(&bhi[q * 4], base + 16384 + off);
                ldsm4t(&blo[q * 4], base + 32768 + off);
            }
            #pragma unroll
            for (int j = 0; j < 8; j++) {
                mma_bf16(acc[j], ahi, &bhi[j * 2]);
                mma_bf16(acc[j], ahi, &blo[j * 2]);
                mma_bf16(acc[j], alo, &bhi[j * 2]);
            }
        }
        __syncthreads();
    }

    // ---- epilogue: +bias, per-head softmax over n (BN=128 = all states) ----
    int r0 = wm * 16 + (l >> 2);
    int cb = wn * 64 + (l & 3) * 2;
    #pragma unroll
    for (int j = 0; j < 8; j++) {
        float b0 = sBias[cb + j * 8], b1 = sBias[cb + j * 8 + 1];
        acc[j][0] += b0; acc[j][1] += b1; acc[j][2] += b0; acc[j][3] += b1;
    }
    float mx0 = -1e30f, mx8 = -1e30f;
    #pragma unroll
    for (int j = 0; j < 8; j++) {
        mx0 = fmaxf(mx0, fmaxf(acc[j][0], acc[j][1]));
        mx8 = fmaxf(mx8, fmaxf(acc[j][2], acc[j][3]));
    }
    mx0 = fmaxf(mx0, __shfl_xor_sync(~0u, mx0, 1));
    mx0 = fmaxf(mx0, __shfl_xor_sync(~0u, mx0, 2));
    mx8 = fmaxf(mx8, __shfl_xor_sync(~0u, mx8, 1));
    mx8 = fmaxf(mx8, __shfl_xor_sync(~0u, mx8, 2));
    if ((l & 3) == 0) { sMax[r0][wn] = mx0; sMax[r0 + 8][wn] = mx8; }
    __syncthreads();
    float M0 = fmaxf(sMax[r0][0], sMax[r0][1]);
    float M8 = fmaxf(sMax[r0 + 8][0], sMax[r0 + 8][1]);
    float s0 = 0.f, s8 = 0.f;
    #pragma unroll
    for (int j = 0; j < 8; j++) {
        acc[j][0] = __expf(acc[j][0] - M0); s0 += acc[j][0];
        acc[j][1] = __expf(acc[j][1] - M0); s0 += acc[j][1];
        acc[j][2] = __expf(acc[j][2] - M8); s8 += acc[j][2];
        acc[j][3] = __expf(acc[j][3] - M8); s8 += acc[j][3];
    }
    s0 += __shfl_xor_sync(~0u, s0, 1); s0 += __shfl_xor_sync(~0u, s0, 2);
    s8 += __shfl_xor_sync(~0u, s8, 1); s8 += __shfl_xor_sync(~0u, s8, 2);
    if ((l & 3) == 0) { sSum[r0][wn] = s0; sSum[r0 + 8][wn] = s8; }
    __syncthreads();
    float inv0 = 1.f / (sSum[r0][0] + sSum[r0][1]);
    float inv8 = 1.f / (sSum[r0 + 8][0] + sSum[r0 + 8][1]);
    __half* wout = g_w + ((size_t)(b * NH + h) * NS + stile * 64) * NN;
    #pragma unroll
    for (int j = 0; j < 8; j++) {
        *(__half2*)(wout + (size_t)r0 * NN + cb + j * 8) =
            __floats2half2_rn(acc[j][0] * inv0, acc[j][1] * inv0);
        *(__half2*)(wout + (size_t)(r0 + 8) * NN + cb + j * 8) =
            __floats2half2_rn(acc[j][2] * inv8, acc[j][3] * inv8);
    }
}

// ============================================================================
// L6 meanent: head-mean + entropy partials (warp-per-row, fp16 reads)
// ============================================================================
__global__ void meanent_kernel(float* __restrict__ out_rout) {
    int t = threadIdx.x, w = t >> 5, l = t & 31;
    int row = blockIdx.x * 8 + w;             // row = b*4096+s
    int b = row >> 12, s = row & 4095;
    size_t hs = (size_t)NS * NN;
    size_t base = ((size_t)(b * NH) * NS + s) * NN + l * 4;
    float a0 = 0.f, a1 = 0.f, a2 = 0.f, a3 = 0.f;
    #pragma unroll
    for (int h = 0; h < NH; h++) {
        const __half2* p = (const __half2*)(g_w + base + h * hs);
        float2 x = __half22float2(p[0]);
        float2 y = __half22float2(p[1]);
        a0 += x.x; a1 += x.y; a2 += y.x; a3 += y.y;
    }
    float4 v = make_float4(a0 * 0.25f, a1 * 0.25f, a2 * 0.25f, a3 * 0.25f);
    *(float4*)(out_rout + (size_t)row * NN + l * 4) = v;
    float c = v.x * __logf(v.x + 1e-8f) + v.y * __logf(v.y + 1e-8f)
            + v.z * __logf(v.z + 1e-8f) + v.w * __logf(v.w + 1e-8f);
    #pragma unroll
    for (int o = 16; o; o >>= 1) c += __shfl_xor_sync(~0u, c, o);
    __shared__ float red[8];
    if (l == 0) red[w] = c;
    __syncthreads();
    if (t == 0) {
        float s2 = 0.f;
        #pragma unroll
        for (int i = 0; i < 8; i++) s2 += red[i];
        g_entpart[blockIdx.x] = s2;
    }
}

// ============================================================================
// L7 fin: final reduce of 2048 partials -> loss scalar
// ============================================================================
__global__ void fin_kernel(float* __restrict__ out) {
    int t = threadIdx.x;
    float s = 0.f;
    #pragma unroll
    for (int i = 0; i < 8; i++) s += g_entpart[i * 256 + t];
    #pragma unroll
    for (int o = 16; o; o >>= 1) s += __shfl_xor_sync(~0u, s, o);
    __shared__ float red[8];
    if ((t & 31) == 0) red[t >> 5] = s;
    __syncthreads();
    if (t == 0) {
        float tot = 0.f;
        #pragma unroll
        for (int i = 0; i < 8; i++) tot += red[i];
        out[0] = tot * (0.01f / (float)NTOK);
    }
}

// ---------------- launch (single stream) -------------------------------------
extern "C" void kernel_launch(void* const* d_in, const int* in_sizes, int n_in,
                              void* d_out, int out_size) {
    (void)in_sizes; (void)n_in; (void)out_size;
    const float* tokens = (const float*)d_in[0];
    const float* states = (const float*)d_in[1];
    const float* ln_t_g = (const float*)d_in[2];
    const float* ln_t_b = (const float*)d_in[3];
    const float* ln_s_g = (const float*)d_in[4];
    const float* ln_s_b = (const float*)d_in[5];
    const float* Wq     = (const float*)d_in[6];
    const float* bq     = (const float*)d_in[7];
    const float* Wk     = (const float*)d_in[8];
    const float* bk     = (const float*)d_in[9];
    const float* temp   = (const float*)d_in[10];
    float* out = (float*)d_out;

    cudaFuncSetAttribute(main_kernel, cudaFuncAttributeMaxDynamicSharedMemorySize, 98304);

    prepA_kernel<<<NB * NN + 32, 256>>>(states, ln_s_g, ln_s_b, Wq, ln_t_b);
    prepB_kernel<<<34, 256>>>(Wk, bk, bq);
    tokln_kernel<<<2048, 256>>>(tokens, out);
    prepC_kernel<<<264, 256>>>(Wq, ln_t_g, temp);     // profiled slot 4
    main_kernel<<<dim3(64, 4, 4), 256, 98304>>>();
    meanent_kernel<<<2048, 256>>>(out + (size_t)NTOK * TD);
    fin_kernel<<<1, 256>>>(out + (size_t)NTOK * TD + (size_t)NTOK * NN);
}